// round 11
// baseline (speedup 1.0000x reference)
#include <cuda_runtime.h>
#include <math.h>

// Problem constants
#define BATCH 8
#define CHAN  256
#define HH    512
#define WW    512
#define POOL  16
#define PH    (HH / POOL)          // 32
#define PW    (WW / POOL)          // 32
#define NPC   (BATCH * PH * PW)    // 8192 pooled elems per channel
#define GRID  (BATCH * CHAN * PH)  // 65536 blocks

// Per-channel moment accumulators: [c][5] = {S1, S2, S11, S22, S12}
// Zero-initialized at module load; finalize_kernel re-zeroes after consuming,
// so every graph replay (and the initial correctness call) starts from zeros.
__device__ float g_acc[CHAN * 5];

// One block per (b, c, ph) slab (16 raw rows x 512 cols). 256 threads = 8 warps.
// Warp w owns pooled columns [4w, 4w+4): float4 colgroups [16w, 16w+16).
// Lane l: rowpar = l>>4 (row parity), colg = 16w + (l&15).
// Each pooled cell (16x16 = 256 elems) is covered by exactly 8 lanes of one
// warp: lanes {4c..4c+3} u {16+4c..16+4c+3}. Pooling is done with shfl_xor
// (16,2,1) -- no shared memory, no __syncthreads in the hot path. Moments are
// then warp-reduced across the 4 cells (shfl_xor 4,8) and atomically added.
__global__ void __launch_bounds__(256, 8)
pool_stats_kernel(const float* __restrict__ f1, const float* __restrict__ f2) {
    const int blk = blockIdx.x;
    const int ph = blk & (PH - 1);          // fastest: contiguous memory across blocks
    const int c  = (blk >> 5) & (CHAN - 1);
    const int b  = blk >> 13;

    const int t = threadIdx.x;
    const int w = t >> 5;
    const int l = t & 31;
    const int rowpar = l >> 4;              // 0 or 1
    const int colg   = (w << 4) | (l & 15); // float4 column group 0..127

    const size_t base = (((size_t)(b * CHAN + c)) * HH + (size_t)ph * POOL) * WW;
    const float4* __restrict__ p1 = (const float4*)(f1 + base);
    const float4* __restrict__ p2 = (const float4*)(f2 + base);

    float a1 = 0.0f, a2 = 0.0f;
#pragma unroll
    for (int it = 0; it < 8; it++) {
        const int row = rowpar + 2 * it;
        const float4 v1 = __ldcs(&p1[row * (WW / 4) + colg]);   // streaming: no reuse
        const float4 v2 = __ldcs(&p2[row * (WW / 4) + colg]);
        a1 += (v1.x + v1.y) + (v1.z + v1.w);
        a2 += (v2.x + v2.y) + (v2.z + v2.w);
    }

    // Combine the 8 lanes of each pooled cell: XOR butterfly over lane bits
    // {16, 2, 1}. Afterwards all 8 lanes of a cell hold the full 256-elem sum.
    a1 += __shfl_xor_sync(0xffffffffu, a1, 16);
    a2 += __shfl_xor_sync(0xffffffffu, a2, 16);
    a1 += __shfl_xor_sync(0xffffffffu, a1, 2);
    a2 += __shfl_xor_sync(0xffffffffu, a2, 2);
    a1 += __shfl_xor_sync(0xffffffffu, a1, 1);
    a2 += __shfl_xor_sync(0xffffffffu, a2, 1);

    const float pv1 = a1 * (1.0f / 256.0f);   // pooled value f1
    const float pv2 = a2 * (1.0f / 256.0f);   // pooled value f2

    float m0 = pv1;
    float m1v = pv2;
    float m2 = pv1 * pv1;
    float m3 = pv2 * pv2;
    float m4 = pv1 * pv2;

    // Sum across the warp's 4 pooled cells (cell id = lane bits {2,3}).
    // XOR over {4, 8} picks exactly one lane per cell group -> no duplication.
#pragma unroll
    for (int off = 4; off <= 8; off <<= 1) {
        m0  += __shfl_xor_sync(0xffffffffu, m0,  off);
        m1v += __shfl_xor_sync(0xffffffffu, m1v, off);
        m2  += __shfl_xor_sync(0xffffffffu, m2,  off);
        m3  += __shfl_xor_sync(0xffffffffu, m3,  off);
        m4  += __shfl_xor_sync(0xffffffffu, m4,  off);
    }
    if (l == 0) {
        atomicAdd(&g_acc[c * 5 + 0], m0);
        atomicAdd(&g_acc[c * 5 + 1], m1v);
        atomicAdd(&g_acc[c * 5 + 2], m2);
        atomicAdd(&g_acc[c * 5 + 3], m3);
        atomicAdd(&g_acc[c * 5 + 4], m4);
    }
    // All moment contributions are published; allow the dependent finalize
    // grid to launch while remaining blocks drain.
    cudaTriggerProgrammaticLaunchCompletion();
}

__global__ void finalize_kernel(float* __restrict__ out) {
    const int c = threadIdx.x;  // 256 threads, one per channel

    // Wait for all pool_stats blocks (PDL); their atomics are then visible.
    cudaGridDependencySynchronize();

    const float n = (float)NPC;

    const float s1v = g_acc[c * 5 + 0];
    const float s2v = g_acc[c * 5 + 1];
    const float s11 = g_acc[c * 5 + 2];
    const float s22 = g_acc[c * 5 + 3];
    const float s12 = g_acc[c * 5 + 4];

    const float mA = s1v / n;
    const float mB = s2v / n;
    const float cov = s12 / n - mA * mB;                 // biased covariance
    const float ssd1 = s11 - s1v * s1v / n;              // sum squared deviations
    const float ssd2 = s22 - s2v * s2v / n;
    const float std1 = sqrtf(fmaxf(ssd1, 0.0f) / (n - 1.0f));  // unbiased std
    const float std2 = sqrtf(fmaxf(ssd2, 0.0f) / (n - 1.0f));
    const float corr = cov / (std1 * std2 + 1e-8f);
    const float a = fabsf(corr);

    __shared__ float red[CHAN];
    red[c] = a;
    __syncthreads();
#pragma unroll
    for (int s = CHAN / 2; s > 0; s >>= 1) {
        if (c < s) red[c] += red[c + s];
        __syncthreads();
    }
    if (c == 0) out[0] = 1.0f - red[0] / (float)CHAN;

    // Re-zero the accumulators for the next graph replay.
#pragma unroll
    for (int q = 0; q < 5; q++) g_acc[c * 5 + q] = 0.0f;
}

extern "C" void kernel_launch(void* const* d_in, const int* in_sizes, int n_in,
                              void* d_out, int out_size) {
    const float* f1 = (const float*)d_in[0];
    const float* f2 = (const float*)d_in[1];
    float* out = (float*)d_out;

    pool_stats_kernel<<<GRID, 256>>>(f1, f2);

    // Finalize with programmatic dependent launch: its launch latency and
    // prologue overlap the main kernel's tail waves.
    cudaLaunchConfig_t cfg = {};
    cfg.gridDim = dim3(1, 1, 1);
    cfg.blockDim = dim3(CHAN, 1, 1);
    cfg.dynamicSmemBytes = 0;
    cfg.stream = 0;
    cudaLaunchAttribute attrs[1];
    attrs[0].id = cudaLaunchAttributeProgrammaticStreamSerialization;
    attrs[0].val.programmaticStreamSerializationAllowed = 1;
    cfg.attrs = attrs;
    cfg.numAttrs = 1;
    cudaLaunchKernelEx(&cfg, finalize_kernel, out);
}

// round 12
// speedup vs baseline: 1.5402x; 1.5402x over previous
#include <cuda_runtime.h>
#include <math.h>

// Problem constants
#define BATCH 8
#define CHAN  256
#define HH    512
#define WW    512
#define POOL  16
#define PH    (HH / POOL)          // 32
#define PW    (WW / POOL)          // 32
#define NPC   (BATCH * PH * PW)    // 8192 pooled elems per channel
#define GRID2 (BATCH * CHAN * PH / 2)  // 32768 blocks, 2 ph-slabs each

// Per-channel moment accumulators: [c][5] = {S1, S2, S11, S22, S12}
// Zero-initialized at module load; finalize_kernel re-zeroes after consuming,
// so every graph replay (and the initial correctness call) starts from zeros.
__device__ float g_acc[CHAN * 5];

// One block per (b, c, ph-pair): two adjacent 16-row slabs = 64 KiB/tensor,
// contiguous. 256 threads. Thread t: rowpar = t>>7 (0/1), colg = t&127
// (float4 group along W) -- identical coalescing to the proven R4 layout
// (one 512B segment per warp-instruction). Each slab's per-thread partials
// (32 floats -> 1 pooled-column partial) go to smem; ONE barrier after both
// slabs; warp 0 reduces both slabs' pooled values into the 5 moments and
// issues exactly 5 global atomics per block (atomic discipline: R5 showed
// that multiplying these 8x costs ~300us in L2 atomic serialization).
__global__ void __launch_bounds__(256, 8)
pool_stats_kernel(const float* __restrict__ f1, const float* __restrict__ f2) {
    const int blk = blockIdx.x;
    const int phpair = blk & (PH / 2 - 1);   // 0..15, fastest: contiguous memory
    const int c  = (blk >> 4) & (CHAN - 1);
    const int b  = blk >> 12;

    const int t = threadIdx.x;
    const int rowpar = t >> 7;     // 0 or 1
    const int colg   = t & 127;    // float4 column group 0..127

    const size_t base0 =
        (((size_t)(b * CHAN + c)) * HH + (size_t)phpair * (2 * POOL)) * WW;

    __shared__ float s1a[256], s2a[256];   // slab 0 partials
    __shared__ float s1b[256], s2b[256];   // slab 1 partials

    // ---- slab 0 ----
    {
        const float4* __restrict__ p1 = (const float4*)(f1 + base0);
        const float4* __restrict__ p2 = (const float4*)(f2 + base0);
        float a1 = 0.0f, a2 = 0.0f;
#pragma unroll
        for (int it = 0; it < 8; it++) {
            const int row = rowpar + 2 * it;
            const float4 v1 = __ldcs(&p1[row * (WW / 4) + colg]);
            const float4 v2 = __ldcs(&p2[row * (WW / 4) + colg]);
            a1 += (v1.x + v1.y) + (v1.z + v1.w);
            a2 += (v2.x + v2.y) + (v2.z + v2.w);
        }
        s1a[t] = a1;
        s2a[t] = a2;
    }

    // ---- slab 1 (next 16 rows; contiguous 32 KiB further) ----
    {
        const float4* __restrict__ p1 = (const float4*)(f1 + base0 + (size_t)POOL * WW);
        const float4* __restrict__ p2 = (const float4*)(f2 + base0 + (size_t)POOL * WW);
        float a1 = 0.0f, a2 = 0.0f;
#pragma unroll
        for (int it = 0; it < 8; it++) {
            const int row = rowpar + 2 * it;
            const float4 v1 = __ldcs(&p1[row * (WW / 4) + colg]);
            const float4 v2 = __ldcs(&p2[row * (WW / 4) + colg]);
            a1 += (v1.x + v1.y) + (v1.z + v1.w);
            a2 += (v2.x + v2.y) + (v2.z + v2.w);
        }
        s1b[t] = a1;
        s2b[t] = a2;
    }

    __syncthreads();

    if (t < PW) {  // 32 threads, one per pooled column (warp 0)
        float m0 = 0.0f, m1v = 0.0f, m2 = 0.0f, m3 = 0.0f, m4 = 0.0f;

        // slab 0 pooled value for column t
        {
            float q1 = 0.0f, q2 = 0.0f;
#pragma unroll
            for (int q = 0; q < 4; q++) {
                q1 += s1a[4 * t + q] + s1a[128 + 4 * t + q];
                q2 += s2a[4 * t + q] + s2a[128 + 4 * t + q];
            }
            const float pv1 = q1 * (1.0f / 256.0f);
            const float pv2 = q2 * (1.0f / 256.0f);
            m0 += pv1; m1v += pv2;
            m2 += pv1 * pv1; m3 += pv2 * pv2; m4 += pv1 * pv2;
        }
        // slab 1 pooled value for column t
        {
            float q1 = 0.0f, q2 = 0.0f;
#pragma unroll
            for (int q = 0; q < 4; q++) {
                q1 += s1b[4 * t + q] + s1b[128 + 4 * t + q];
                q2 += s2b[4 * t + q] + s2b[128 + 4 * t + q];
            }
            const float pv1 = q1 * (1.0f / 256.0f);
            const float pv2 = q2 * (1.0f / 256.0f);
            m0 += pv1; m1v += pv2;
            m2 += pv1 * pv1; m3 += pv2 * pv2; m4 += pv1 * pv2;
        }

#pragma unroll
        for (int off = 16; off > 0; off >>= 1) {
            m0  += __shfl_down_sync(0xffffffffu, m0,  off);
            m1v += __shfl_down_sync(0xffffffffu, m1v, off);
            m2  += __shfl_down_sync(0xffffffffu, m2,  off);
            m3  += __shfl_down_sync(0xffffffffu, m3,  off);
            m4  += __shfl_down_sync(0xffffffffu, m4,  off);
        }
        if (t == 0) {
            atomicAdd(&g_acc[c * 5 + 0], m0);
            atomicAdd(&g_acc[c * 5 + 1], m1v);
            atomicAdd(&g_acc[c * 5 + 2], m2);
            atomicAdd(&g_acc[c * 5 + 3], m3);
            atomicAdd(&g_acc[c * 5 + 4], m4);
        }
    }
    // All moment contributions are published; allow the dependent finalize
    // grid to launch while remaining blocks drain.
    cudaTriggerProgrammaticLaunchCompletion();
}

__global__ void finalize_kernel(float* __restrict__ out) {
    const int c = threadIdx.x;  // 256 threads, one per channel

    // Wait for all pool_stats blocks (PDL); their atomics are then visible.
    cudaGridDependencySynchronize();

    const float n = (float)NPC;

    const float s1v = g_acc[c * 5 + 0];
    const float s2v = g_acc[c * 5 + 1];
    const float s11 = g_acc[c * 5 + 2];
    const float s22 = g_acc[c * 5 + 3];
    const float s12 = g_acc[c * 5 + 4];

    const float mA = s1v / n;
    const float mB = s2v / n;
    const float cov = s12 / n - mA * mB;                 // biased covariance
    const float ssd1 = s11 - s1v * s1v / n;              // sum squared deviations
    const float ssd2 = s22 - s2v * s2v / n;
    const float std1 = sqrtf(fmaxf(ssd1, 0.0f) / (n - 1.0f));  // unbiased std
    const float std2 = sqrtf(fmaxf(ssd2, 0.0f) / (n - 1.0f));
    const float corr = cov / (std1 * std2 + 1e-8f);
    const float a = fabsf(corr);

    __shared__ float red[CHAN];
    red[c] = a;
    __syncthreads();
#pragma unroll
    for (int s = CHAN / 2; s > 0; s >>= 1) {
        if (c < s) red[c] += red[c + s];
        __syncthreads();
    }
    if (c == 0) out[0] = 1.0f - red[0] / (float)CHAN;

    // Re-zero the accumulators for the next graph replay.
#pragma unroll
    for (int q = 0; q < 5; q++) g_acc[c * 5 + q] = 0.0f;
}

extern "C" void kernel_launch(void* const* d_in, const int* in_sizes, int n_in,
                              void* d_out, int out_size) {
    const float* f1 = (const float*)d_in[0];
    const float* f2 = (const float*)d_in[1];
    float* out = (float*)d_out;

    pool_stats_kernel<<<GRID2, 256>>>(f1, f2);

    // Finalize with programmatic dependent launch: its launch latency and
    // prologue overlap the main kernel's tail waves.
    cudaLaunchConfig_t cfg = {};
    cfg.gridDim = dim3(1, 1, 1);
    cfg.blockDim = dim3(CHAN, 1, 1);
    cfg.dynamicSmemBytes = 0;
    cfg.stream = 0;
    cudaLaunchAttribute attrs[1];
    attrs[0].id = cudaLaunchAttributeProgrammaticStreamSerialization;
    attrs[0].val.programmaticStreamSerializationAllowed = 1;
    cfg.attrs = attrs;
    cfg.numAttrs = 1;
    cudaLaunchKernelEx(&cfg, finalize_kernel, out);
}